// round 1
// baseline (speedup 1.0000x reference)
#include <cuda_runtime.h>

// Problem constants
#define BN   8
#define DD   64
#define NN   3136          // H*W = 56*56
#define KK   32
#define TPB  448           // 14 warps; 448*7 = 3136 exactly
#define ITEMS 7

__device__ float g_EM[BN * DD];     // (1/K) * sum_n E[b,n,d]
__device__ float g_gamma[BN * DD];  // sigmoid(EM @ fc_w^T + fc_b)

__device__ __forceinline__ float ex2f(float x) {
    float r;
    asm("ex2.approx.ftz.f32 %0, %1;" : "=f"(r) : "f"(x));
    return r;
}

// Kernel 1: one block per (b,d). Computes E[b,d,:] into out (scratch) and the
// row-sum into g_EM. E = x - (sum_k e_k * c_k) / (sum_k e_k), with
// e_k = exp2(a_k*x^2 + b_k*x + cc_k), a=scale*log2e, b=-2ac, cc=ac^2.
__global__ __launch_bounds__(TPB)
void enc_main(const float* __restrict__ X,
              const float* __restrict__ codewords,
              const float* __restrict__ scale,
              float* __restrict__ out)
{
    __shared__ float sA[KK], sB[KK], sC[KK], sCW[KK];
    const int bd  = blockIdx.x;          // b*64 + d
    const int d   = bd & (DD - 1);
    const int tid = threadIdx.x;

    if (tid < KK) {
        const float L2E = 1.4426950408889634f;
        float s = scale[tid * DD + d] * L2E;
        float c = codewords[tid * DD + d];
        sA[tid]  = s;
        sB[tid]  = -2.0f * s * c;
        sC[tid]  = s * c * c;
        sCW[tid] = c;
    }
    __syncthreads();

    const float* xrow = X + (size_t)bd * NN;
    float xs[ITEMS], se[ITEMS], sc[ITEMS];
    #pragma unroll
    for (int j = 0; j < ITEMS; j++) {
        xs[j] = xrow[tid + j * TPB];
        se[j] = 0.0f;
        sc[j] = 0.0f;
    }

    #pragma unroll 4
    for (int k = 0; k < KK; k++) {
        float a = sA[k], b = sB[k], c = sC[k], cw = sCW[k];
        #pragma unroll
        for (int j = 0; j < ITEMS; j++) {
            float t = fmaf(fmaf(a, xs[j], b), xs[j], c);
            float e = ex2f(t);
            se[j] += e;
            sc[j] = fmaf(e, cw, sc[j]);
        }
    }

    float esum = 0.0f;
    float* orow = out + (size_t)bd * NN;
    #pragma unroll
    for (int j = 0; j < ITEMS; j++) {
        float E = xs[j] - sc[j] / se[j];
        orow[tid + j * TPB] = E;
        esum += E;
    }

    // block reduction of esum -> g_EM[bd]
    #pragma unroll
    for (int off = 16; off; off >>= 1)
        esum += __shfl_xor_sync(0xffffffffu, esum, off);
    __shared__ float wsum[TPB / 32];
    const int wid = tid >> 5;
    if ((tid & 31) == 0) wsum[wid] = esum;
    __syncthreads();
    if (tid == 0) {
        float s = 0.0f;
        #pragma unroll
        for (int i = 0; i < TPB / 32; i++) s += wsum[i];
        g_EM[bd] = s * (1.0f / KK);
    }
}

// Kernel 2: gamma[b,d] = sigmoid(sum_d' EM[b,d'] * fc_w[d,d'] + fc_b[d])
__global__ __launch_bounds__(BN * DD)
void enc_gamma(const float* __restrict__ fc_w, const float* __restrict__ fc_b)
{
    __shared__ float sEM[BN * DD];
    const int tid = threadIdx.x;     // 0..511
    sEM[tid] = g_EM[tid];
    __syncthreads();
    const int b = tid >> 6;
    const int d = tid & 63;
    float acc = fc_b[d];
    const float* wrow = fc_w + d * DD;
    #pragma unroll
    for (int i = 0; i < DD; i++)
        acc = fmaf(sEM[b * DD + i], wrow[i], acc);
    g_gamma[tid] = 1.0f / (1.0f + __expf(-acc));
}

// Kernel 3: out = relu(E * (1 + gamma[b,d])), in-place on out.
__global__ __launch_bounds__(TPB)
void enc_final(float* __restrict__ out)
{
    const int bd = blockIdx.x;
    const float g = 1.0f + g_gamma[bd];
    float* orow = out + (size_t)bd * NN;
    const int tid = threadIdx.x;
    #pragma unroll
    for (int j = 0; j < ITEMS; j++) {
        const int i = tid + j * TPB;
        float v = orow[i] * g;
        orow[i] = v > 0.0f ? v : 0.0f;
    }
}

extern "C" void kernel_launch(void* const* d_in, const int* in_sizes, int n_in,
                              void* d_out, int out_size)
{
    const float* X   = (const float*)d_in[0];
    const float* cw  = (const float*)d_in[1];
    const float* sc  = (const float*)d_in[2];
    const float* fw  = (const float*)d_in[3];
    const float* fb  = (const float*)d_in[4];
    float* out = (float*)d_out;

    enc_main <<<BN * DD, TPB>>>(X, cw, sc, out);
    enc_gamma<<<1, BN * DD>>>(fw, fb);
    enc_final<<<BN * DD, TPB>>>(out);
}

// round 4
// speedup vs baseline: 1.7097x; 1.7097x over previous
#include <cuda_runtime.h>

// Problem constants
#define BN    8
#define DD    64
#define NN    3136         // H*W = 56*56
#define KK    32
#define TPB   448          // 14 warps; 448*7 = 3136 exactly
#define ITEMS 7
#define NBLK  128          // persistent: one block per SM (<=148), all resident
#define RPB   4            // rows (bd pairs) per block: 128*4 = 512 = B*D

__device__ float    g_EM[BN * DD];   // (1/K) * sum_n E[b,n,d]
__device__ unsigned g_count = 0;     // monotonic epoch barrier counter

__device__ __forceinline__ float ex2f(float x) {
    float r;
    asm("ex2.approx.ftz.f32 %0, %1;" : "=f"(r) : "f"(x));
    return r;
}

__device__ __forceinline__ unsigned ld_acquire(const unsigned* p) {
    unsigned v;
    asm volatile("ld.global.acquire.gpu.u32 %0, [%1];" : "=r"(v) : "l"(p));
    return v;
}

__device__ __forceinline__ float ldcg_f(const float* p) {
    float v;
    asm volatile("ld.global.cg.f32 %0, [%1];" : "=f"(v) : "l"(p));
    return v;
}

// One fused persistent kernel.
// Phase 1: per row bd, E[n] = x - (sum_k e_k c_k)/(sum_k e_k),
//          e_k = exp2(a x^2 + b x + c); E kept in registers; row-sum -> g_EM.
// Grid barrier (all 128 blocks resident).
// Phase 2: gamma for this block's 4 rows (same b).
// Phase 3: out = relu(E * (1 + gamma)).
__global__ __launch_bounds__(TPB, 1)
void enc_fused(const float* __restrict__ X,
               const float* __restrict__ codewords,
               const float* __restrict__ scale,
               const float* __restrict__ fc_w,
               const float* __restrict__ fc_b,
               float* __restrict__ out)
{
    __shared__ float sA[KK], sB[KK], sC[KK], sCW[KK];
    __shared__ float wsum[TPB / 32];
    __shared__ float sEM[DD];
    __shared__ float sG[RPB];

    const int tid = threadIdx.x;
    const int bd0 = blockIdx.x * RPB;       // 4 consecutive bd, same b
    const int b   = bd0 >> 6;

    float Ereg[RPB][ITEMS];

    for (int r = 0; r < RPB; r++) {
        const int bd = bd0 + r;
        const int d  = bd & (DD - 1);

        __syncthreads();                    // protect smem reuse across rows
        if (tid < KK) {
            const float L2E = 1.4426950408889634f;
            float s = scale[tid * DD + d] * L2E;
            float c = codewords[tid * DD + d];
            sA[tid]  = s;
            sB[tid]  = -2.0f * s * c;
            sC[tid]  = s * c * c;
            sCW[tid] = c;
        }
        __syncthreads();

        const float* xrow = X + (size_t)bd * NN;
        float xs[ITEMS], se[ITEMS], sc[ITEMS];
        #pragma unroll
        for (int j = 0; j < ITEMS; j++) {
            xs[j] = xrow[tid + j * TPB];
            se[j] = 0.0f;
            sc[j] = 0.0f;
        }

        #pragma unroll 4
        for (int k = 0; k < KK; k++) {
            float a = sA[k], bb = sB[k], c = sC[k], cw = sCW[k];
            #pragma unroll
            for (int j = 0; j < ITEMS; j++) {
                float t = fmaf(fmaf(a, xs[j], bb), xs[j], c);
                float e = ex2f(t);
                se[j] += e;
                sc[j] = fmaf(e, cw, sc[j]);
            }
        }

        float esum = 0.0f;
        #pragma unroll
        for (int j = 0; j < ITEMS; j++) {
            float E = xs[j] - sc[j] / se[j];
            Ereg[r][j] = E;
            esum += E;
        }

        #pragma unroll
        for (int off = 16; off; off >>= 1)
            esum += __shfl_xor_sync(0xffffffffu, esum, off);
        const int wid = tid >> 5;
        if ((tid & 31) == 0) wsum[wid] = esum;
        __syncthreads();
        if (tid == 0) {
            float s = 0.0f;
            #pragma unroll
            for (int i = 0; i < TPB / 32; i++) s += wsum[i];
            g_EM[bd] = s * (1.0f / KK);
        }
    }

    // ---- grid barrier (all NBLK blocks resident; epoch counter, no reset) ----
    __threadfence();                         // publish g_EM
    __syncthreads();                         // all threads' work done
    if (tid == 0) {
        unsigned old = atomicAdd(&g_count, 1u);
        unsigned target = (old / NBLK + 1u) * NBLK;
        while (ld_acquire(&g_count) < target)
            __nanosleep(64);
    }
    __syncthreads();

    // ---- gamma for this block's 4 rows ----
    if (tid < DD) sEM[tid] = ldcg_f(&g_EM[b * DD + tid]);  // bypass L1 (cross-SM data)
    __syncthreads();
    if (tid < RPB) {
        const int d = (bd0 + tid) & (DD - 1);
        float acc = fc_b[d];
        const float* wrow = fc_w + d * DD;
        #pragma unroll
        for (int i = 0; i < DD; i++)
            acc = fmaf(sEM[i], wrow[i], acc);
        sG[tid] = 1.0f + 1.0f / (1.0f + __expf(-acc));     // 1 + sigmoid
    }
    __syncthreads();

    // ---- final: out = relu(E * (1 + gamma)) ----
    #pragma unroll
    for (int r = 0; r < RPB; r++) {
        const float g = sG[r];
        float* orow = out + (size_t)(bd0 + r) * NN;
        #pragma unroll
        for (int j = 0; j < ITEMS; j++) {
            float v = Ereg[r][j] * g;
            orow[tid + j * TPB] = v > 0.0f ? v : 0.0f;
        }
    }
}

extern "C" void kernel_launch(void* const* d_in, const int* in_sizes, int n_in,
                              void* d_out, int out_size)
{
    const float* X  = (const float*)d_in[0];
    const float* cw = (const float*)d_in[1];
    const float* sc = (const float*)d_in[2];
    const float* fw = (const float*)d_in[3];
    const float* fb = (const float*)d_in[4];
    float* out = (float*)d_out;

    enc_fused<<<NBLK, TPB>>>(X, cw, sc, fw, fb, out);
}

// round 6
// speedup vs baseline: 1.7789x; 1.0405x over previous
#include <cuda_runtime.h>

// Problem constants
#define BN    8
#define DD    64
#define NN    3136         // H*W = 56*56
#define KK    32
#define TPB   512          // 16 warps -> exactly 4 per SMSP (balanced MUFU)
#define NPAIR 3            // 3 float2 pairs/thread = 6 items; 512*6 = 3072
#define REM   64           // remainder 3136-3072, handled by tid<64 (warps 0-1)
#define NBLK  128          // persistent: one block per SM, all resident
#define RPB   4            // rows per block: 128*4 = 512 = B*D

typedef unsigned long long ull;

__device__ float    g_EM[BN * DD];
__device__ unsigned g_count = 0;    // monotonic epoch barrier (graph-replay safe)

__device__ __forceinline__ float ex2f(float x) {
    float r;
    asm("ex2.approx.ftz.f32 %0, %1;" : "=f"(r) : "f"(x));
    return r;
}
__device__ __forceinline__ ull pack2(float lo, float hi) {
    ull r;
    asm("mov.b64 %0, {%1, %2};" : "=l"(r) : "f"(lo), "f"(hi));
    return r;
}
__device__ __forceinline__ void unpack2(ull v, float& lo, float& hi) {
    asm("mov.b64 {%0, %1}, %2;" : "=f"(lo), "=f"(hi) : "l"(v));
}
__device__ __forceinline__ ull fma2(ull a, ull b, ull c) {
    ull r;
    asm("fma.rn.f32x2 %0, %1, %2, %3;" : "=l"(r) : "l"(a), "l"(b), "l"(c));
    return r;
}
__device__ __forceinline__ ull add2(ull a, ull b) {
    ull r;
    asm("add.rn.f32x2 %0, %1, %2;" : "=l"(r) : "l"(a), "l"(b));
    return r;
}
__device__ __forceinline__ unsigned ld_acquire(const unsigned* p) {
    unsigned v;
    asm volatile("ld.global.acquire.gpu.u32 %0, [%1];" : "=r"(v) : "l"(p));
    return v;
}
__device__ __forceinline__ float ldcg_f(const float* p) {
    float v;
    asm volatile("ld.global.cg.f32 %0, [%1];" : "=f"(v) : "l"(p));
    return v;
}

__global__ __launch_bounds__(TPB, 1)
void enc_fused(const float* __restrict__ X,
               const float* __restrict__ codewords,
               const float* __restrict__ scale,
               const float* __restrict__ fc_w,
               const float* __restrict__ fc_b,
               float* __restrict__ out)
{
    __shared__ ull sA2[RPB][KK], sB2[RPB][KK], sC2[RPB][KK], sCW2[RPB][KK];
    __shared__ float sAs[RPB][KK], sBs[RPB][KK], sCs[RPB][KK], sCWs[RPB][KK];
    __shared__ float wsum[TPB / 32];
    __shared__ float sEM[DD];
    __shared__ float sG[RPB];

    const int tid = threadIdx.x;
    const int bd0 = blockIdx.x * RPB;    // 4 consecutive bd, same b
    const int b   = bd0 >> 6;

    // ---- preload ALL rows' constants once (packed + scalar copies) ----
    if (tid < RPB * KK) {
        const int r = tid >> 5, k = tid & 31;
        const int d = (bd0 + r) & (DD - 1);
        const float L2E = 1.4426950408889634f;
        float s = scale[k * DD + d] * L2E;
        float c = codewords[k * DD + d];
        float bb = -2.0f * s * c;
        float cc = s * c * c;
        sA2[r][k]  = pack2(s,  s);
        sB2[r][k]  = pack2(bb, bb);
        sC2[r][k]  = pack2(cc, cc);
        sCW2[r][k] = pack2(c,  c);
        sAs[r][k]  = s;
        sBs[r][k]  = bb;
        sCs[r][k]  = cc;
        sCWs[r][k] = c;
    }
    __syncthreads();

    // ---- load row 0 X (pairs n = 2*tid + p*1024 -> LDG.64 coalesced) ----
    ull x2c[NPAIR]; float xec = 0.0f;
    {
        const float2* xrow = (const float2*)(X + (size_t)bd0 * NN);
        #pragma unroll
        for (int p = 0; p < NPAIR; p++) {
            float2 v = xrow[tid + p * TPB];
            x2c[p] = pack2(v.x, v.y);
        }
        if (tid < REM) xec = X[(size_t)bd0 * NN + 2 * NPAIR * TPB + tid];
    }

    float Ereg[RPB][2 * NPAIR];
    float Eex[RPB];

    #pragma unroll
    for (int r = 0; r < RPB; r++) {
        const int bd = bd0 + r;

        // prefetch next row's X behind this row's k-loop
        ull x2n[NPAIR]; float xen = 0.0f;
        if (r + 1 < RPB) {
            const float2* xrow = (const float2*)(X + (size_t)(bd + 1) * NN);
            #pragma unroll
            for (int p = 0; p < NPAIR; p++) {
                float2 v = xrow[tid + p * TPB];
                x2n[p] = pack2(v.x, v.y);
            }
            if (tid < REM) xen = X[(size_t)(bd + 1) * NN + 2 * NPAIR * TPB + tid];
        }

        ull se2[NPAIR], sc2[NPAIR];
        #pragma unroll
        for (int p = 0; p < NPAIR; p++) { se2[p] = 0ull; sc2[p] = 0ull; }

        #pragma unroll 4
        for (int k = 0; k < KK; k++) {
            ull a2 = sA2[r][k], b2 = sB2[r][k], c2 = sC2[r][k], cw2 = sCW2[r][k];
            #pragma unroll
            for (int p = 0; p < NPAIR; p++) {
                ull t2 = fma2(fma2(a2, x2c[p], b2), x2c[p], c2);
                float tl, th; unpack2(t2, tl, th);
                ull e2 = pack2(ex2f(tl), ex2f(th));
                se2[p] = add2(se2[p], e2);
                sc2[p] = fma2(e2, cw2, sc2[p]);
            }
        }

        // remainder: warps 0-1 only, scalar pass on scalar constant copies
        float seE = 0.0f, scE = 0.0f;
        if (tid < REM) {
            #pragma unroll 4
            for (int k = 0; k < KK; k++) {
                float t = fmaf(fmaf(sAs[r][k], xec, sBs[r][k]), xec, sCs[r][k]);
                float e = ex2f(t);
                seE += e;
                scE = fmaf(e, sCWs[r][k], scE);
            }
        }

        // epilogue: E = x - sc/se, keep in regs; row-sum -> g_EM
        float esum = 0.0f;
        #pragma unroll
        for (int p = 0; p < NPAIR; p++) {
            float sel, seh, scl, sch, xl, xh;
            unpack2(se2[p], sel, seh);
            unpack2(sc2[p], scl, sch);
            unpack2(x2c[p], xl, xh);
            float El = xl - __fdividef(scl, sel);
            float Eh = xh - __fdividef(sch, seh);
            Ereg[r][2 * p]     = El;
            Ereg[r][2 * p + 1] = Eh;
            esum += El + Eh;
        }
        if (tid < REM) {
            float Ee = xec - __fdividef(scE, seE);
            Eex[r] = Ee;
            esum += Ee;
        } else {
            Eex[r] = 0.0f;
        }

        #pragma unroll
        for (int off = 16; off; off >>= 1)
            esum += __shfl_xor_sync(0xffffffffu, esum, off);
        const int wid = tid >> 5;
        if ((tid & 31) == 0) wsum[wid] = esum;
        __syncthreads();
        if (tid == 0) {
            float s = 0.0f;
            #pragma unroll
            for (int i = 0; i < TPB / 32; i++) s += wsum[i];
            g_EM[bd] = s * (1.0f / KK);
        }
        __syncthreads();   // protect wsum reuse next row

        // rotate prefetched X
        #pragma unroll
        for (int p = 0; p < NPAIR; p++) x2c[p] = x2n[p];
        xec = xen;
    }

    // ---- grid barrier (all NBLK blocks resident; epoch counter, no reset) ----
    __threadfence();
    __syncthreads();
    if (tid == 0) {
        unsigned old = atomicAdd(&g_count, 1u);
        unsigned target = (old / NBLK + 1u) * NBLK;
        while (ld_acquire(&g_count) < target)
            __nanosleep(64);
    }
    __syncthreads();

    // ---- gamma for this block's 4 rows (same b) ----
    if (tid < DD) sEM[tid] = ldcg_f(&g_EM[b * DD + tid]);
    __syncthreads();
    if (tid < RPB) {
        const int d = (bd0 + tid) & (DD - 1);
        float acc = fc_b[d];
        const float* wrow = fc_w + d * DD;
        #pragma unroll
        for (int i = 0; i < DD; i++)
            acc = fmaf(sEM[i], wrow[i], acc);
        sG[tid] = 1.0f + 1.0f / (1.0f + __expf(-acc));   // 1 + sigmoid
    }
    __syncthreads();

    // ---- final: out = relu(E * (1 + gamma)), STG.64 pairs ----
    #pragma unroll
    for (int r = 0; r < RPB; r++) {
        const float g = sG[r];
        float2* orow = (float2*)(out + (size_t)(bd0 + r) * NN);
        #pragma unroll
        for (int p = 0; p < NPAIR; p++) {
            float vx = Ereg[r][2 * p]     * g;
            float vy = Ereg[r][2 * p + 1] * g;
            float2 v;
            v.x = vx > 0.0f ? vx : 0.0f;
            v.y = vy > 0.0f ? vy : 0.0f;
            orow[tid + p * TPB] = v;
        }
        if (tid < REM) {
            float v = Eex[r] * g;
            out[(size_t)(bd0 + r) * NN + 2 * NPAIR * TPB + tid] = v > 0.0f ? v : 0.0f;
        }
    }
}

extern "C" void kernel_launch(void* const* d_in, const int* in_sizes, int n_in,
                              void* d_out, int out_size)
{
    const float* X  = (const float*)d_in[0];
    const float* cw = (const float*)d_in[1];
    const float* sc = (const float*)d_in[2];
    const float* fw = (const float*)d_in[3];
    const float* fb = (const float*)d_in[4];
    float* out = (float*)d_out;

    enc_fused<<<NBLK, TPB>>>(X, cw, sc, fw, fb, out);
}

// round 7
// speedup vs baseline: 1.7815x; 1.0014x over previous
#include <cuda_runtime.h>

// Problem constants
#define BN     8
#define DD     64
#define NN     3136        // H*W
#define KK     32
#define TPB    512         // 16 warps, 4 per SMSP
#define ITEMS  3           // 512*3 = 1536 of 1568
#define HALF   1568        // NN/2
#define REMOFF 1536        // tail of a half-row: 32 elems
#define NBLK   148         // persistent blocks, all resident
#define MAXU   7           // ceil(1024/148)
#define NU     1024        // 512 rows * 2 halves

__device__ float    g_EMp[NU];   // per-unit partial sum of E (main 1536 elems)
__device__ float    g_EMr[NU];   // per-unit partial sum of E (tail 32 elems)
__device__ unsigned g_count = 0; // monotonic epoch barrier (graph-replay safe)

__device__ __forceinline__ float ex2f(float x) {
    float r;
    asm("ex2.approx.ftz.f32 %0, %1;" : "=f"(r) : "f"(x));
    return r;
}
__device__ __forceinline__ unsigned ld_acquire(const unsigned* p) {
    unsigned v;
    asm volatile("ld.global.acquire.gpu.u32 %0, [%1];" : "=r"(v) : "l"(p));
    return v;
}
__device__ __forceinline__ float ldcg_f(const float* p) {
    float v;
    asm volatile("ld.global.cg.f32 %0, [%1];" : "=f"(v) : "l"(p));
    return v;
}
__device__ __forceinline__ size_t ubase(int u) {
    return (size_t)(u >> 1) * NN + (size_t)(u & 1) * HALF;
}

__global__ __launch_bounds__(TPB, 1)
void enc_fused(const float* __restrict__ X,
               const float* __restrict__ codewords,
               const float* __restrict__ scale,
               const float* __restrict__ fc_w,
               const float* __restrict__ fc_b,
               float* __restrict__ out)
{
    __shared__ float4 cst[MAXU][KK];        // (a, b, c, cw) per unit per k
    __shared__ float  wsum[2][TPB / 32];
    __shared__ float  sG[MAXU];

    const int tid  = threadIdx.x;
    const int bid  = blockIdx.x;
    const int nunits = (NU - bid + NBLK - 1) / NBLK;   // 7 or 6
    const int wid  = tid >> 5;
    const int lane = tid & 31;

    // ---- issue unit0 X loads + this thread's tail element early ----
    float xc[ITEMS];
    {
        const float* b0 = X + ubase(bid);
        #pragma unroll
        for (int i = 0; i < ITEMS; i++) xc[i] = b0[tid + i * TPB];
    }
    float xrem = 0.0f;
    if (wid < nunits)
        xrem = X[ubase(bid + wid * NBLK) + REMOFF + lane];

    // ---- preload ALL units' constants once ----
    if (tid < nunits * KK) {                 // <= 224 threads
        const int j = tid >> 5, k = tid & 31;
        const int d = ((bid + j * NBLK) >> 1) & (DD - 1);
        const float L2E = 1.4426950408889634f;
        float s = scale[k * DD + d] * L2E;
        float c = codewords[k * DD + d];
        cst[j][k] = make_float4(s, -2.0f * s * c, s * c * c, c);
    }
    __syncthreads();

    // ---- tail pass: warp w handles unit w's 32 tail elems ----
    float Erem = 0.0f;
    if (wid < nunits) {
        float se = 0.0f, sc_ = 0.0f;
        #pragma unroll 4
        for (int k = 0; k < KK; k++) {
            float4 q = cst[wid][k];
            float t = fmaf(fmaf(q.x, xrem, q.y), xrem, q.z);
            float e = ex2f(t);
            se += e;
            sc_ = fmaf(e, q.w, sc_);
        }
        Erem = xrem - __fdividef(sc_, se);
        float rs = Erem;
        #pragma unroll
        for (int off = 16; off; off >>= 1)
            rs += __shfl_xor_sync(0xffffffffu, rs, off);
        if (lane == 0) g_EMr[bid + wid * NBLK] = rs;
    }

    // ---- main units: uniform 3 elems/thread, k-loop on MUFU ----
    float Ereg[MAXU][ITEMS];

    for (int j = 0; j < nunits; j++) {
        const int u = bid + j * NBLK;

        // prefetch next unit's X behind this unit's k-loop
        float xn[ITEMS];
        const bool more = (j + 1 < nunits);
        if (more) {
            const float* bn = X + ubase(u + NBLK);
            #pragma unroll
            for (int i = 0; i < ITEMS; i++) xn[i] = bn[tid + i * TPB];
        }

        float se[ITEMS], scc[ITEMS];
        #pragma unroll
        for (int i = 0; i < ITEMS; i++) { se[i] = 0.0f; scc[i] = 0.0f; }

        #pragma unroll 4
        for (int k = 0; k < KK; k++) {
            float4 q = cst[j][k];
            #pragma unroll
            for (int i = 0; i < ITEMS; i++) {
                float t = fmaf(fmaf(q.x, xc[i], q.y), xc[i], q.z);
                float e = ex2f(t);
                se[i] += e;
                scc[i] = fmaf(e, q.w, scc[i]);
            }
        }

        float esum = 0.0f;
        #pragma unroll
        for (int i = 0; i < ITEMS; i++) {
            float E = xc[i] - __fdividef(scc[i], se[i]);
            Ereg[j][i] = E;
            esum += E;
        }

        #pragma unroll
        for (int off = 16; off; off >>= 1)
            esum += __shfl_xor_sync(0xffffffffu, esum, off);
        if (lane == 0) wsum[j & 1][wid] = esum;
        __syncthreads();                     // single sync per unit (parity buffers)
        if (tid == 0) {
            float s = 0.0f;
            #pragma unroll
            for (int w = 0; w < TPB / 32; w++) s += wsum[j & 1][w];
            g_EMp[u] = s;
        }

        if (more) {
            #pragma unroll
            for (int i = 0; i < ITEMS; i++) xc[i] = xn[i];
        }
    }

    // ---- grid barrier (148 blocks, all resident; monotonic epoch) ----
    __threadfence();
    __syncthreads();
    if (tid == 0) {
        unsigned old = atomicAdd(&g_count, 1u);
        unsigned target = (old / NBLK + 1u) * NBLK;
        while (ld_acquire(&g_count) < target)
            __nanosleep(64);
    }
    __syncthreads();

    // ---- gamma: warp w computes gamma for unit w's row ----
    if (wid < nunits) {
        const int u  = bid + wid * NBLK;
        const int bd = u >> 1;
        const int b  = bd >> 6;
        const int d  = bd & (DD - 1);
        const float inv_k = 1.0f / KK;

        int i0 = b * DD + lane;
        int i1 = i0 + 32;
        float em0 = (ldcg_f(&g_EMp[2 * i0]) + ldcg_f(&g_EMp[2 * i0 + 1]) +
                     ldcg_f(&g_EMr[2 * i0]) + ldcg_f(&g_EMr[2 * i0 + 1])) * inv_k;
        float em1 = (ldcg_f(&g_EMp[2 * i1]) + ldcg_f(&g_EMp[2 * i1 + 1]) +
                     ldcg_f(&g_EMr[2 * i1]) + ldcg_f(&g_EMr[2 * i1 + 1])) * inv_k;

        float t = fmaf(em0, fc_w[d * DD + lane],
                       em1 * fc_w[d * DD + lane + 32]);
        #pragma unroll
        for (int off = 16; off; off >>= 1)
            t += __shfl_xor_sync(0xffffffffu, t, off);
        if (lane == 0)
            sG[wid] = 1.0f + 1.0f / (1.0f + __expf(-(t + fc_b[d])));
    }
    __syncthreads();

    // ---- final: out = relu(E * (1 + gamma)) ----
    for (int j = 0; j < nunits; j++) {
        const float g = sG[j];
        float* ob = out + ubase(bid + j * NBLK);
        #pragma unroll
        for (int i = 0; i < ITEMS; i++) {
            float v = Ereg[j][i] * g;
            ob[tid + i * TPB] = v > 0.0f ? v : 0.0f;
        }
    }
    if (wid < nunits) {
        float v = Erem * sG[wid];
        out[ubase(bid + wid * NBLK) + REMOFF + lane] = v > 0.0f ? v : 0.0f;
    }
}

extern "C" void kernel_launch(void* const* d_in, const int* in_sizes, int n_in,
                              void* d_out, int out_size)
{
    const float* X  = (const float*)d_in[0];
    const float* cw = (const float*)d_in[1];
    const float* sc = (const float*)d_in[2];
    const float* fw = (const float*)d_in[3];
    const float* fb = (const float*)d_in[4];
    float* out = (float*)d_out;

    enc_fused<<<NBLK, TPB>>>(X, cw, sc, fw, fb, out);
}